// round 12
// baseline (speedup 1.0000x reference)
#include <cuda_runtime.h>
#include <stdint.h>

// Problem: B=64, C=256, H=64, W=64, k=8.  out: [64, 8, 259] fp32
#define BB   64
#define CC   256
#define HH   64
#define WW   64
#define NPB  (1 << 20)          // elements per batch (C*H*W)
#define KK   8
#define OUTC (CC + 3)           // 259
#define CAP  16384              // candidate capacity per batch

#define CH     16               // filter chunks per batch (total-best shape)
#define CHUNK  (NPB / CH)       // 65536 elements
#define TPB    256
#define GROUPS 8                // per-thread groups of 32 elems (8*32*256 = 65536)

#define TSL      64             // threshold slices per batch
#define SLICE_E  2048           // elements per disjoint slice (64*2048 = 128K sampled)
#define TPB_T    256

typedef unsigned long long u64;
typedef unsigned int u32;

__device__ u64 g_cand[BB * CAP];     // 8 MB scratch (static, allocation-free)
__device__ int g_count[BB];
__device__ int g_done[BB];
__device__ int g_tdone[BB];          // thresh completion (self-resetting per launch)
__device__ u32 g_tmono[BB * TSL];    // per-slice maxes (monotonic encoding)
__device__ u32 g_tb[BB];             // bit threshold for fast unsigned compare
__device__ float g_tf[BB];           // float threshold (exact compare)

// monotonic float<->uint mapping (total order matches float compare)
__device__ __forceinline__ u32 f2mono(float f) {
    u32 b = __float_as_uint(f);
    return b ^ ((u32)((int)b >> 31) | 0x80000000u);
}
__device__ __forceinline__ float mono2f(u32 m) {
    u32 b = (m & 0x80000000u) ? (m ^ 0x80000000u) : ~m;
    return __uint_as_float(b);
}
__device__ __forceinline__ u64 make_key(float v, u32 idx) {
    return ((u64)f2mono(v) << 32) | (u32)(~idx);
}

// exact top-8 insert by key (value desc, index asc) — matches lax.top_k
__device__ __forceinline__ void consider_key(u64 (&top)[KK], u64 key) {
    if (key > top[KK - 1]) {
        top[KK - 1] = key;
        #pragma unroll
        for (int j = KK - 1; j > 0; --j) {
            if (top[j] > top[j - 1]) { u64 t = top[j]; top[j] = top[j - 1]; top[j - 1] = t; }
        }
    }
}

// ── Pass A: slice maxes + in-kernel combine: T = 8th-largest of 64 maxes ────
// 64 disjoint 2K slices. The 8 largest slice-maxes are >= T at 8 distinct
// positions → T <= true 8th-largest element for ANY input: filter never drops
// a true top-8 element.
__global__ __launch_bounds__(TPB_T)
void k_thresh(const float* __restrict__ x) {
    const int b = blockIdx.x;
    const int s = blockIdx.y;
    const int tid = threadIdx.x;
    if (s == 0 && tid == 0) { g_count[b] = 0; g_done[b] = 0; }

    const float4* __restrict__ p =
        (const float4*)(x + (size_t)b * NPB + (size_t)s * SLICE_E);
    const float NEG_INF = -__int_as_float(0x7f800000);

    float m0 = NEG_INF, m1 = NEG_INF;
    {   // SLICE_E/(TPB_T*4) = 2 float4 per thread
        float4 v0 = p[tid];
        float4 v1 = p[TPB_T + tid];
        m0 = fmaxf(fmaxf(v0.x, v0.y), fmaxf(v0.z, v0.w));
        m1 = fmaxf(fmaxf(v1.x, v1.y), fmaxf(v1.z, v1.w));
    }
    float m = fmaxf(m0, m1);

    #pragma unroll
    for (int off = 16; off > 0; off >>= 1)
        m = fmaxf(m, __shfl_xor_sync(0xFFFFFFFFu, m, off));
    __shared__ float wm[TPB_T / 32];
    const int lane = tid & 31, warp = tid >> 5;
    if (lane == 0) wm[warp] = m;
    __syncthreads();

    if (tid == 0) {
        float mm = wm[0];
        #pragma unroll
        for (int w = 1; w < TPB_T / 32; ++w) mm = fmaxf(mm, wm[w]);
        g_tmono[b * TSL + s] = f2mono(mm);
        __threadfence();                       // release slice max
        int d = atomicAdd(&g_tdone[b], 1);
        if (d == TSL - 1) {
            // last slice of batch b: combine — 8th-largest of 64 slice maxes
            __threadfence();                   // acquire
            u32 top8[KK];
            #pragma unroll
            for (int j = 0; j < KK; ++j) top8[j] = 0u;
            for (int i = 0; i < TSL; ++i) {
                u32 v = __ldcg(&g_tmono[b * TSL + i]);
                if (v > top8[KK - 1]) {
                    top8[KK - 1] = v;
                    #pragma unroll
                    for (int j = KK - 1; j > 0; --j)
                        if (top8[j] > top8[j - 1]) {
                            u32 t = top8[j]; top8[j] = top8[j - 1]; top8[j - 1] = t;
                        }
                }
            }
            u32 t8 = top8[KK - 1];             // 8th-largest mono
            g_tf[b] = mono2f(t8);
            g_tb[b] = (t8 >= 0x80000000u) ? (t8 ^ 0x80000000u) : 0u;
            g_tdone[b] = 0;                    // self-reset for next graph replay
        }
    }
}

// ───────────── selection (runs inside the last filter block per batch) ──────
// Reader side of the release/acquire pair: g_cand / g_count reads via __ldcg
// (L2) so they cannot hit stale L1 lines; writers published with
// st → __threadfence → __syncthreads → atomicAdd(done).
__device__ void do_select(int b, const float* __restrict__ x,
                          float* __restrict__ out) {
    const int tid = threadIdx.x;
    const int cnt = __ldcg(&g_count[b]);

    u64 top[KK];
    #pragma unroll
    for (int j = 0; j < KK; ++j) top[j] = 0ull;

    if (cnt >= KK && cnt <= CAP) {
        for (int i = tid; i < cnt; i += TPB)
            consider_key(top, __ldcg(&g_cand[b * CAP + i]));
    } else {
        // fallback: exact brute-force scan of the whole batch (cold path)
        const float4* __restrict__ p = (const float4*)(x + (size_t)b * NPB);
        for (int i = tid; i < NPB / 4; i += TPB) {
            float4 v = p[i];
            u32 e = (u32)i * 4u;
            consider_key(top, make_key(v.x, e + 0u));
            consider_key(top, make_key(v.y, e + 1u));
            consider_key(top, make_key(v.z, e + 2u));
            consider_key(top, make_key(v.w, e + 3u));
        }
    }

    __shared__ u64 cand[TPB * KK];
    __shared__ u64 wmax[TPB / 32];
    __shared__ u64 winner;
    __shared__ u64 topk[KK];
    #pragma unroll
    for (int j = 0; j < KK; ++j) cand[tid * KK + j] = top[j];
    __syncthreads();

    const int lane = tid & 31, warp = tid >> 5;
    for (int sel = 0; sel < KK; ++sel) {
        u64 m = 0ull;
        #pragma unroll
        for (int j = 0; j < KK; ++j) { u64 cc = cand[tid * KK + j]; if (cc > m) m = cc; }
        #pragma unroll
        for (int off = 16; off > 0; off >>= 1) {
            u64 o = __shfl_down_sync(0xFFFFFFFFu, m, off);
            if (o > m) m = o;
        }
        if (lane == 0) wmax[warp] = m;
        __syncthreads();
        if (tid == 0) {
            u64 w = 0ull;
            #pragma unroll
            for (int q = 0; q < TPB / 32; ++q) if (wmax[q] > w) w = wmax[q];
            winner = w;
            topk[sel] = w;
        }
        __syncthreads();
        u64 w = winner;
        #pragma unroll
        for (int j = 0; j < KK; ++j)
            if (cand[tid * KK + j] == w) cand[tid * KK + j] = 0ull;
        __syncthreads();
    }

    float* ob = out + (size_t)b * KK * OUTC;
    for (int i = tid; i < KK * OUTC; i += TPB) ob[i] = 0.0f;
    __syncthreads();

    if (tid < KK) {
        u64 k = topk[tid];
        float val = mono2f((u32)(k >> 32));
        u32 idx = ~((u32)k);
        int ci  = (int)(idx >> 12);
        int rem = (int)(idx & 4095u);
        int y   = rem >> 6;
        int xq  = rem & 63;
        float* row = ob + tid * OUTC;
        row[ci]     = 1.0f;
        row[CC + 0] = val;
        row[CC + 1] = (float)xq * (1.0f / (WW - 1));
        row[CC + 2] = (float)y  * (1.0f / (HH - 1));
    }
}

// ───────────── Pass B: stream + filter + compact (+ fused select) ───────────
__device__ __forceinline__ void emit(int b, float v, u32 idx) {
    int s = atomicAdd(&g_count[b], 1);
    if (s < CAP) g_cand[b * CAP + s] = make_key(v, idx);
}

__global__ __launch_bounds__(TPB, 6)      // low regs → 6 blocks/SM
void k_filter(const float* __restrict__ x, float* __restrict__ out) {
    const int c = blockIdx.x;
    const int b = blockIdx.y;
    const int tid = threadIdx.x;

    // thresholds computed by previous kernel (L1 flushed at launch boundary)
    const u32 TB  = g_tb[b];
    const float TF = g_tf[b];

    const u32 cbase = (u32)c * CHUNK;
    const uint4* __restrict__ p = (const uint4*)(x + (size_t)b * NPB + cbase);

    for (int i = 0; i < GROUPS; ++i) {
        // Fast path keeps ONLY the 8 quad-maxes live; the slow path reloads
        // element values via __ldcg (L2 hit) — small live range, no spills.
        u32 m4[8];
        #pragma unroll
        for (int j = 0; j < 8; ++j) {
            uint4 qq = p[(i * 8 + j) * TPB + tid];
            m4[j] = umax(__vimax3_u32(qq.x, qq.y, qq.z), qq.w);
        }
        // Unsigned bit compare is exact for non-negative floats; negatives/NaN
        // compare high -> false positives only (rechecked exactly below).
        u32 r0 = __vimax3_u32(m4[0], m4[1], m4[2]);
        u32 r1 = __vimax3_u32(m4[3], m4[4], m4[5]);
        u32 r2 = __vimax3_u32(m4[6], m4[7], r0);
        u32 mm = umax(r1, r2);

        if (mm >= TB) {
            #pragma unroll
            for (int j = 0; j < 8; ++j) {
                if (m4[j] >= TB) {
                    uint4 qv = __ldcg(&p[(i * 8 + j) * TPB + tid]);  // L2 reload
                    u32 e = cbase + ((u32)(i * 8 + j) * TPB + (u32)tid) * 4u;
                    float v0f = __uint_as_float(qv.x);
                    float v1f = __uint_as_float(qv.y);
                    float v2f = __uint_as_float(qv.z);
                    float v3f = __uint_as_float(qv.w);
                    if (v0f >= TF) emit(b, v0f, e + 0u);
                    if (v1f >= TF) emit(b, v1f, e + 1u);
                    if (v2f >= TF) emit(b, v2f, e + 2u);
                    if (v3f >= TF) emit(b, v3f, e + 3u);
                }
            }
        }
    }

    // fused select, threadFenceReduction pattern:
    //   per-thread: stores → __threadfence (device-visible)
    //   __syncthreads: ALL threads' fences complete before tid0's atomic
    //   tid0: atomicAdd(done)  — the release is block-wide
    __threadfence();
    __syncthreads();
    __shared__ int is_last;
    if (tid == 0) is_last = (atomicAdd(&g_done[b], 1) == CH - 1) ? 1 : 0;
    __syncthreads();
    if (is_last) {
        __threadfence();          // acquire: order candidate reads after the
                                  // observed done-count
        do_select(b, x, out);
    }
}

extern "C" void kernel_launch(void* const* d_in, const int* in_sizes, int n_in,
                              void* d_out, int out_size) {
    const float* x = (const float*)d_in[0];
    float* out = (float*)d_out;

    dim3 gt(BB, TSL);
    k_thresh<<<gt, TPB_T>>>(x);
    dim3 gf(CH, BB);
    k_filter<<<gf, TPB>>>(x, out);
}

// round 13
// speedup vs baseline: 1.0969x; 1.0969x over previous
#include <cuda_runtime.h>
#include <stdint.h>

// Problem: B=64, C=256, H=64, W=64, k=8.  out: [64, 8, 259] fp32
#define BB   64
#define CC   256
#define HH   64
#define WW   64
#define NPB  (1 << 20)          // elements per batch (C*H*W)
#define KK   8
#define OUTC (CC + 3)           // 259
#define CAP  16384              // candidate capacity per batch

#define CH     16               // filter chunks per batch (best total shape)
#define CHUNK  (NPB / CH)       // 65536 elements
#define TPB    256
#define GROUPS 8                // per-thread groups of 32 elems

#define TSL      64             // threshold slices per batch
#define SLICE_E  2048           // elements per slice (8 MB sampled total)
#define TPB_T    256

typedef unsigned long long u64;
typedef unsigned int u32;

__device__ u64 g_cand[BB * CAP];     // 8 MB scratch (static, allocation-free)
__device__ int g_count[BB];
__device__ int g_done[BB];
__device__ int g_tdone[BB];          // thresh completion (self-resetting)
__device__ u32 g_tmono[BB * TSL];    // per-slice maxes (monotonic encoding)
__device__ u32 g_tb[BB];             // bit threshold (unsigned fast compare)
__device__ float g_tf[BB];           // float threshold (exact compare)

// monotonic float<->uint mapping (total order matches float compare)
__device__ __forceinline__ u32 f2mono(float f) {
    u32 b = __float_as_uint(f);
    return b ^ ((u32)((int)b >> 31) | 0x80000000u);
}
__device__ __forceinline__ float mono2f(u32 m) {
    u32 b = (m & 0x80000000u) ? (m ^ 0x80000000u) : ~m;
    return __uint_as_float(b);
}
__device__ __forceinline__ u64 make_key(float v, u32 idx) {
    return ((u64)f2mono(v) << 32) | (u32)(~idx);
}
__device__ __forceinline__ u32 qmax(uint4 q) {
    return umax(__vimax3_u32(q.x, q.y, q.z), q.w);
}

// exact top-8 insert by key (value desc, index asc) — matches lax.top_k
__device__ __forceinline__ void consider_key(u64 (&top)[KK], u64 key) {
    if (key > top[KK - 1]) {
        top[KK - 1] = key;
        #pragma unroll
        for (int j = KK - 1; j > 0; --j) {
            if (top[j] > top[j - 1]) { u64 t = top[j]; top[j] = top[j - 1]; top[j - 1] = t; }
        }
    }
}

// ── Pass A: slice maxes; last block combines T = 8th-largest of 64 maxes ────
// 64 disjoint 2K slices. The 8 largest slice-maxes sit at >=8 distinct
// positions, all >= T → T <= true 8th-largest element for ANY input.
// (Duplicate maxes only lower the extracted T — still valid.)
__global__ __launch_bounds__(TPB_T)
void k_thresh(const float* __restrict__ x) {
    const int b = blockIdx.x;
    const int s = blockIdx.y;
    const int tid = threadIdx.x;
    if (s == 0 && tid == 0) { g_count[b] = 0; g_done[b] = 0; }

    const float4* __restrict__ p =
        (const float4*)(x + (size_t)b * NPB + (size_t)s * SLICE_E);

    float m0, m1;
    {   // 2 float4 per thread
        float4 v0 = p[tid];
        float4 v1 = p[TPB_T + tid];
        m0 = fmaxf(fmaxf(v0.x, v0.y), fmaxf(v0.z, v0.w));
        m1 = fmaxf(fmaxf(v1.x, v1.y), fmaxf(v1.z, v1.w));
    }
    float m = fmaxf(m0, m1);

    #pragma unroll
    for (int off = 16; off > 0; off >>= 1)
        m = fmaxf(m, __shfl_xor_sync(0xFFFFFFFFu, m, off));
    __shared__ float wm[TPB_T / 32];
    const int lane = tid & 31, warp = tid >> 5;
    if (lane == 0) wm[warp] = m;
    __syncthreads();

    __shared__ int lastf;
    if (tid == 0) {
        float mm = wm[0];
        #pragma unroll
        for (int w = 1; w < TPB_T / 32; ++w) mm = fmaxf(mm, wm[w]);
        g_tmono[b * TSL + s] = f2mono(mm);
        __threadfence();                       // release slice max
        lastf = (atomicAdd(&g_tdone[b], 1) == TSL - 1) ? 1 : 0;
    }
    __syncthreads();

    if (lastf && tid < 32) {
        __threadfence();                       // acquire
        // warp 0: parallel 8th-largest of the 64 slice maxes
        u32 a = __ldcg(&g_tmono[b * TSL + tid]);
        u32 c = __ldcg(&g_tmono[b * TSL + 32 + tid]);
        u32 t8 = 0;
        #pragma unroll
        for (int sel = 0; sel < KK; ++sel) {
            u32 mx = umax(a, c);
            #pragma unroll
            for (int off = 16; off > 0; off >>= 1)
                mx = umax(mx, __shfl_xor_sync(0xFFFFFFFFu, mx, off));
            t8 = mx;
            if (a == mx) a = 0u;               // removes dups too: only lowers T
            if (c == mx) c = 0u;
        }
        if (tid == 0) {
            g_tf[b] = mono2f(t8);
            g_tb[b] = (t8 >= 0x80000000u) ? (t8 ^ 0x80000000u) : 0u;
            g_tdone[b] = 0;                    // self-reset for graph replays
        }
    }
}

// ───────────── selection (runs inside the last filter block per batch) ──────
// Reader side of the release/acquire pair: g_cand / g_count reads via __ldcg
// (L2) so they cannot hit stale L1 lines; writers published with
// st → __threadfence → __syncthreads → atomicAdd(done).
__device__ void do_select(int b, const float* __restrict__ x,
                          float* __restrict__ out) {
    const int tid = threadIdx.x;
    const int cnt = __ldcg(&g_count[b]);

    u64 top[KK];
    #pragma unroll
    for (int j = 0; j < KK; ++j) top[j] = 0ull;

    if (cnt >= KK && cnt <= CAP) {
        for (int i = tid; i < cnt; i += TPB)
            consider_key(top, __ldcg(&g_cand[b * CAP + i]));
    } else {
        // fallback: exact brute-force scan of the whole batch (cold path)
        const float4* __restrict__ p = (const float4*)(x + (size_t)b * NPB);
        for (int i = tid; i < NPB / 4; i += TPB) {
            float4 v = p[i];
            u32 e = (u32)i * 4u;
            consider_key(top, make_key(v.x, e + 0u));
            consider_key(top, make_key(v.y, e + 1u));
            consider_key(top, make_key(v.z, e + 2u));
            consider_key(top, make_key(v.w, e + 3u));
        }
    }

    __shared__ u64 cand[TPB * KK];
    __shared__ u64 wmax[TPB / 32];
    __shared__ u64 winner;
    __shared__ u64 topk[KK];
    #pragma unroll
    for (int j = 0; j < KK; ++j) cand[tid * KK + j] = top[j];
    __syncthreads();

    const int lane = tid & 31, warp = tid >> 5;
    for (int sel = 0; sel < KK; ++sel) {
        u64 m = 0ull;
        #pragma unroll
        for (int j = 0; j < KK; ++j) { u64 cc = cand[tid * KK + j]; if (cc > m) m = cc; }
        #pragma unroll
        for (int off = 16; off > 0; off >>= 1) {
            u64 o = __shfl_down_sync(0xFFFFFFFFu, m, off);
            if (o > m) m = o;
        }
        if (lane == 0) wmax[warp] = m;
        __syncthreads();
        if (tid == 0) {
            u64 w = 0ull;
            #pragma unroll
            for (int q = 0; q < TPB / 32; ++q) if (wmax[q] > w) w = wmax[q];
            winner = w;
            topk[sel] = w;
        }
        __syncthreads();
        u64 w = winner;
        #pragma unroll
        for (int j = 0; j < KK; ++j)
            if (cand[tid * KK + j] == w) cand[tid * KK + j] = 0ull;
        __syncthreads();
    }

    float* ob = out + (size_t)b * KK * OUTC;
    for (int i = tid; i < KK * OUTC; i += TPB) ob[i] = 0.0f;
    __syncthreads();

    if (tid < KK) {
        u64 k = topk[tid];
        float val = mono2f((u32)(k >> 32));
        u32 idx = ~((u32)k);
        int ci  = (int)(idx >> 12);
        int rem = (int)(idx & 4095u);
        int y   = rem >> 6;
        int xq  = rem & 63;
        float* row = ob + tid * OUTC;
        row[ci]     = 1.0f;
        row[CC + 0] = val;
        row[CC + 1] = (float)xq * (1.0f / (WW - 1));
        row[CC + 2] = (float)y  * (1.0f / (HH - 1));
    }
}

// ───────────── Pass B: stream + filter + compact (+ fused select) ───────────
__device__ __forceinline__ void emit(int b, float v, u32 idx) {
    int s = atomicAdd(&g_count[b], 1);
    if (s < CAP) g_cand[b * CAP + s] = make_key(v, idx);
}

__global__ __launch_bounds__(TPB, 5)      // <=51 regs → 5 blocks/SM, 40 warps
void k_filter(const float* __restrict__ x, float* __restrict__ out) {
    const int c = blockIdx.x;
    const int b = blockIdx.y;
    const int tid = threadIdx.x;

    const u32 TB  = g_tb[b];
    const float TF = g_tf[b];

    const u32 cbase = (u32)c * CHUNK;
    const uint4* __restrict__ p = (const uint4*)(x + (size_t)b * NPB + cbase);

    for (int i = 0; i < GROUPS; ++i) {
        const uint4* pi = p + i * 8 * TPB + tid;
        // FRONT-BATCHED loads: all 8 LDG.128 issued before any consume → MLP=8.
        uint4 a0 = pi[0 * TPB];
        uint4 a1 = pi[1 * TPB];
        uint4 a2 = pi[2 * TPB];
        uint4 a3 = pi[3 * TPB];
        uint4 a4 = pi[4 * TPB];
        uint4 a5 = pi[5 * TPB];
        uint4 a6 = pi[6 * TPB];
        uint4 a7 = pi[7 * TPB];

        // Unsigned bit compare is exact for non-negative floats; negatives/NaN
        // compare high -> false positives only (rechecked exactly below).
        u32 m4[8];
        m4[0] = qmax(a0); m4[1] = qmax(a1); m4[2] = qmax(a2); m4[3] = qmax(a3);
        m4[4] = qmax(a4); m4[5] = qmax(a5); m4[6] = qmax(a6); m4[7] = qmax(a7);
        u32 r0 = __vimax3_u32(m4[0], m4[1], m4[2]);
        u32 r1 = __vimax3_u32(m4[3], m4[4], m4[5]);
        u32 r2 = __vimax3_u32(m4[6], m4[7], r0);
        u32 mm = umax(r1, r2);

        if (mm >= TB) {
            #pragma unroll
            for (int j = 0; j < 8; ++j) {
                if (m4[j] >= TB) {
                    uint4 qv = __ldcg(&pi[j * TPB]);   // L2 reload (rare path)
                    u32 e = cbase + ((u32)(i * 8 + j) * TPB + (u32)tid) * 4u;
                    float v0f = __uint_as_float(qv.x);
                    float v1f = __uint_as_float(qv.y);
                    float v2f = __uint_as_float(qv.z);
                    float v3f = __uint_as_float(qv.w);
                    if (v0f >= TF) emit(b, v0f, e + 0u);
                    if (v1f >= TF) emit(b, v1f, e + 1u);
                    if (v2f >= TF) emit(b, v2f, e + 2u);
                    if (v3f >= TF) emit(b, v3f, e + 3u);
                }
            }
        }
    }

    // fused select, threadFenceReduction pattern:
    //   per-thread: stores → __threadfence (device-visible)
    //   __syncthreads: ALL threads' fences complete before tid0's atomic
    //   tid0: atomicAdd(done)  — the release is block-wide
    __threadfence();
    __syncthreads();
    __shared__ int is_last;
    if (tid == 0) is_last = (atomicAdd(&g_done[b], 1) == CH - 1) ? 1 : 0;
    __syncthreads();
    if (is_last) {
        __threadfence();          // acquire: order candidate reads after the
                                  // observed done-count
        do_select(b, x, out);
    }
}

extern "C" void kernel_launch(void* const* d_in, const int* in_sizes, int n_in,
                              void* d_out, int out_size) {
    const float* x = (const float*)d_in[0];
    float* out = (float*)d_out;

    dim3 gt(BB, TSL);
    k_thresh<<<gt, TPB_T>>>(x);
    dim3 gf(CH, BB);
    k_filter<<<gf, TPB>>>(x, out);
}

// round 15
// speedup vs baseline: 1.1746x; 1.0708x over previous
#include <cuda_runtime.h>
#include <stdint.h>

// Problem: B=64, C=256, H=64, W=64, k=8.  out: [64, 8, 259] fp32
#define BB   64
#define CC   256
#define HH   64
#define WW   64
#define NPB  (1 << 20)          // elements per batch (C*H*W)
#define KK   8
#define OUTC (CC + 3)           // 259
#define CAP  16384              // candidate capacity per batch

#define CH     16               // filter chunks per batch (best total shape, R9)
#define CHUNK  (NPB / CH)       // 65536 elements
#define TPB    256
#define GROUPS 8                // per-thread groups of 32 elems

#define TSL      64             // threshold slices per batch
#define SLICE_E  2048           // elements per slice (8 MB sampled total)
#define TPB_T    256

typedef unsigned long long u64;
typedef unsigned int u32;

__device__ u64 g_cand[BB * CAP];     // 8 MB scratch (static, allocation-free)
__device__ int g_count[BB];
__device__ int g_done[BB];
__device__ int g_tdone[BB];          // thresh completion (self-resetting)
__device__ u32 g_tmono[BB * TSL];    // per-slice maxes (monotonic encoding)
__device__ u32 g_tb[BB];             // bit threshold (unsigned fast compare)
__device__ float g_tf[BB];           // float threshold (exact compare)

// monotonic float<->uint mapping (total order matches float compare)
__device__ __forceinline__ u32 f2mono(float f) {
    u32 b = __float_as_uint(f);
    return b ^ ((u32)((int)b >> 31) | 0x80000000u);
}
__device__ __forceinline__ float mono2f(u32 m) {
    u32 b = (m & 0x80000000u) ? (m ^ 0x80000000u) : ~m;
    return __uint_as_float(b);
}
__device__ __forceinline__ u64 make_key(float v, u32 idx) {
    return ((u64)f2mono(v) << 32) | (u32)(~idx);
}

// exact top-8 insert by key (value desc, index asc) — matches lax.top_k
__device__ __forceinline__ void consider_key(u64 (&top)[KK], u64 key) {
    if (key > top[KK - 1]) {
        top[KK - 1] = key;
        #pragma unroll
        for (int j = KK - 1; j > 0; --j) {
            if (top[j] > top[j - 1]) { u64 t = top[j]; top[j] = top[j - 1]; top[j - 1] = t; }
        }
    }
}

// ── Pass A: slice maxes; last block combines T = 8th-largest of 64 maxes ────
// 64 disjoint 2K slices per batch. The 8 largest slice-maxes sit at >=8
// distinct positions, all >= T → T <= true 8th-largest element for ANY input:
// the filter never drops a true top-8 element. (Joint removal of duplicate
// max values in the extract loop only lowers T — still valid.)
__global__ __launch_bounds__(TPB_T)
void k_thresh(const float* __restrict__ x) {
    const int b = blockIdx.x;
    const int s = blockIdx.y;
    const int tid = threadIdx.x;
    if (s == 0 && tid == 0) { g_count[b] = 0; g_done[b] = 0; }

    const float4* __restrict__ p =
        (const float4*)(x + (size_t)b * NPB + (size_t)s * SLICE_E);

    float m0, m1;
    {   // 2 float4 per thread
        float4 v0 = p[tid];
        float4 v1 = p[TPB_T + tid];
        m0 = fmaxf(fmaxf(v0.x, v0.y), fmaxf(v0.z, v0.w));
        m1 = fmaxf(fmaxf(v1.x, v1.y), fmaxf(v1.z, v1.w));
    }
    float m = fmaxf(m0, m1);

    #pragma unroll
    for (int off = 16; off > 0; off >>= 1)
        m = fmaxf(m, __shfl_xor_sync(0xFFFFFFFFu, m, off));
    __shared__ float wm[TPB_T / 32];
    const int lane = tid & 31, warp = tid >> 5;
    if (lane == 0) wm[warp] = m;
    __syncthreads();

    __shared__ int lastf;
    if (tid == 0) {
        float mm = wm[0];
        #pragma unroll
        for (int w = 1; w < TPB_T / 32; ++w) mm = fmaxf(mm, wm[w]);
        g_tmono[b * TSL + s] = f2mono(mm);
        __threadfence();                       // release slice max
        lastf = (atomicAdd(&g_tdone[b], 1) == TSL - 1) ? 1 : 0;
    }
    __syncthreads();

    if (lastf && tid < 32) {
        __threadfence();                       // acquire
        // warp 0: parallel 8th-largest of the 64 slice maxes
        u32 a = __ldcg(&g_tmono[b * TSL + tid]);
        u32 c = __ldcg(&g_tmono[b * TSL + 32 + tid]);
        u32 t8 = 0;
        #pragma unroll
        for (int sel = 0; sel < KK; ++sel) {
            u32 mx = umax(a, c);
            #pragma unroll
            for (int off = 16; off > 0; off >>= 1)
                mx = umax(mx, __shfl_xor_sync(0xFFFFFFFFu, mx, off));
            t8 = mx;
            if (a == mx) a = 0u;
            if (c == mx) c = 0u;
        }
        if (tid == 0) {
            g_tf[b] = mono2f(t8);
            g_tb[b] = (t8 >= 0x80000000u) ? (t8 ^ 0x80000000u) : 0u;
            g_tdone[b] = 0;                    // self-reset for graph replays
        }
    }
}

// ───────────── selection (runs inside the last filter block per batch) ──────
// Reader side of the release/acquire pair: g_cand / g_count reads via __ldcg
// (L2) so they cannot hit stale L1 lines; writers published with
// st → __threadfence → __syncthreads → atomicAdd(done).
__device__ void do_select(int b, const float* __restrict__ x,
                          float* __restrict__ out) {
    const int tid = threadIdx.x;
    const int cnt = __ldcg(&g_count[b]);

    u64 top[KK];
    #pragma unroll
    for (int j = 0; j < KK; ++j) top[j] = 0ull;

    if (cnt >= KK && cnt <= CAP) {
        for (int i = tid; i < cnt; i += TPB)
            consider_key(top, __ldcg(&g_cand[b * CAP + i]));
    } else {
        // fallback: exact brute-force scan of the whole batch (cold path)
        const float4* __restrict__ p = (const float4*)(x + (size_t)b * NPB);
        for (int i = tid; i < NPB / 4; i += TPB) {
            float4 v = p[i];
            u32 e = (u32)i * 4u;
            consider_key(top, make_key(v.x, e + 0u));
            consider_key(top, make_key(v.y, e + 1u));
            consider_key(top, make_key(v.z, e + 2u));
            consider_key(top, make_key(v.w, e + 3u));
        }
    }

    __shared__ u64 cand[TPB * KK];
    __shared__ u64 wmax[TPB / 32];
    __shared__ u64 winner;
    __shared__ u64 topk[KK];
    #pragma unroll
    for (int j = 0; j < KK; ++j) cand[tid * KK + j] = top[j];
    __syncthreads();

    const int lane = tid & 31, warp = tid >> 5;
    for (int sel = 0; sel < KK; ++sel) {
        u64 m = 0ull;
        #pragma unroll
        for (int j = 0; j < KK; ++j) { u64 cc = cand[tid * KK + j]; if (cc > m) m = cc; }
        #pragma unroll
        for (int off = 16; off > 0; off >>= 1) {
            u64 o = __shfl_down_sync(0xFFFFFFFFu, m, off);
            if (o > m) m = o;
        }
        if (lane == 0) wmax[warp] = m;
        __syncthreads();
        if (tid == 0) {
            u64 w = 0ull;
            #pragma unroll
            for (int q = 0; q < TPB / 32; ++q) if (wmax[q] > w) w = wmax[q];
            winner = w;
            topk[sel] = w;
        }
        __syncthreads();
        u64 w = winner;
        #pragma unroll
        for (int j = 0; j < KK; ++j)
            if (cand[tid * KK + j] == w) cand[tid * KK + j] = 0ull;
        __syncthreads();
    }

    float* ob = out + (size_t)b * KK * OUTC;
    for (int i = tid; i < KK * OUTC; i += TPB) ob[i] = 0.0f;
    __syncthreads();

    if (tid < KK) {
        u64 k = topk[tid];
        float val = mono2f((u32)(k >> 32));
        u32 idx = ~((u32)k);
        int ci  = (int)(idx >> 12);
        int rem = (int)(idx & 4095u);
        int y   = rem >> 6;
        int xq  = rem & 63;
        float* row = ob + tid * OUTC;
        row[ci]     = 1.0f;
        row[CC + 0] = val;
        row[CC + 1] = (float)xq * (1.0f / (WW - 1));
        row[CC + 2] = (float)y  * (1.0f / (HH - 1));
    }
}

// ───────────── Pass B: stream + filter + compact (+ fused select) ───────────
// EXACT round-9 filter body (measured best): q[8] kept live, used directly in
// the slow path; no reload, no occupancy cap.
__device__ __forceinline__ void emit(int b, float v, u32 idx) {
    int s = atomicAdd(&g_count[b], 1);
    if (s < CAP) g_cand[b * CAP + s] = make_key(v, idx);
}

__global__ __launch_bounds__(TPB)
void k_filter(const float* __restrict__ x, float* __restrict__ out) {
    const int c = blockIdx.x;
    const int b = blockIdx.y;
    const int tid = threadIdx.x;

    const u32 TB  = g_tb[b];
    const float TF = g_tf[b];

    const u32 cbase = (u32)c * CHUNK;
    const uint4* __restrict__ p = (const uint4*)(x + (size_t)b * NPB + cbase);

    #pragma unroll 4
    for (int i = 0; i < GROUPS; ++i) {
        uint4 q[8];
        #pragma unroll
        for (int j = 0; j < 8; ++j)
            q[j] = p[(i * 8 + j) * TPB + tid];

        // per-q 4-element max (vimax3 + umax), then reduce the 8 partials.
        // Unsigned bit compare is exact for non-negative floats; negatives/NaN
        // compare high -> false positives only (rechecked exactly below).
        u32 m4[8];
        #pragma unroll
        for (int j = 0; j < 8; ++j)
            m4[j] = umax(__vimax3_u32(q[j].x, q[j].y, q[j].z), q[j].w);
        u32 r0 = __vimax3_u32(m4[0], m4[1], m4[2]);
        u32 r1 = __vimax3_u32(m4[3], m4[4], m4[5]);
        u32 r2 = __vimax3_u32(m4[6], m4[7], r0);
        u32 mm = umax(r1, r2);

        if (mm >= TB) {
            // narrowed slow path: only expand quads that can contain a survivor
            #pragma unroll
            for (int j = 0; j < 8; ++j) {
                if (m4[j] >= TB) {
                    u32 e = cbase + ((u32)(i * 8 + j) * TPB + (u32)tid) * 4u;
                    float v0f = __uint_as_float(q[j].x);
                    float v1f = __uint_as_float(q[j].y);
                    float v2f = __uint_as_float(q[j].z);
                    float v3f = __uint_as_float(q[j].w);
                    if (v0f >= TF) emit(b, v0f, e + 0u);
                    if (v1f >= TF) emit(b, v1f, e + 1u);
                    if (v2f >= TF) emit(b, v2f, e + 2u);
                    if (v3f >= TF) emit(b, v3f, e + 3u);
                }
            }
        }
    }

    // fused select, threadFenceReduction pattern:
    //   per-thread: stores → __threadfence (device-visible)
    //   __syncthreads: ALL threads' fences complete before tid0's atomic
    //   tid0: atomicAdd(done)  — the release is block-wide
    __threadfence();
    __syncthreads();
    __shared__ int is_last;
    if (tid == 0) is_last = (atomicAdd(&g_done[b], 1) == CH - 1) ? 1 : 0;
    __syncthreads();
    if (is_last) {
        __threadfence();          // acquire: order candidate reads after the
                                  // observed done-count
        do_select(b, x, out);
    }
}

extern "C" void kernel_launch(void* const* d_in, const int* in_sizes, int n_in,
                              void* d_out, int out_size) {
    const float* x = (const float*)d_in[0];
    float* out = (float*)d_out;

    dim3 gt(BB, TSL);
    k_thresh<<<gt, TPB_T>>>(x);
    dim3 gf(CH, BB);
    k_filter<<<gf, TPB>>>(x, out);
}